// round 6
// baseline (speedup 1.0000x reference)
#include <cuda_runtime.h>
#include <cuda_bf16.h>
#include <cstdint>

// ============================ Problem constants ============================
#define VTAGS 50257
#define BATCH 2048
#define EMB   128
#define NCTX  10
#define NTILES 393            // ceil(50257/128)

// ============================ Scratch (device globals) =====================
__device__ __nv_bfloat16 g_v_bf16[BATCH * EMB];            // pooled code vectors, bf16
__device__ __nv_bfloat16 g_tag_bf16[VTAGS * EMB];          // tag embedding, bf16
__device__ float g_partials[NTILES * BATCH];               // per (ntile, row) sumexp
__device__ float g_inv_sum[BATCH];                         // 1 / sumexp per row

// ============================ helpers ======================================
__device__ __forceinline__ uint32_t smem_to_u32(const void* smem_ptr) {
    uint32_t addr;
    asm("{ .reg .u64 tmp; cvta.to.shared.u64 tmp, %1; cvt.u32.u64 %0, tmp; }"
        : "=r"(addr) : "l"(smem_ptr));
    return addr;
}

// streaming store (evict-first): keep L2 for the bf16 tag matrix
__device__ __forceinline__ void stg_cs(float* p, float v) {
    asm volatile("st.global.cs.f32 [%0], %1;" :: "l"(p), "f"(v) : "memory");
}

#define LDMATRIX_X4(r, addr) \
    asm volatile("ldmatrix.sync.aligned.m8n8.x4.shared.b16 {%0,%1,%2,%3}, [%4];" \
        : "=r"((r)[0]), "=r"((r)[1]), "=r"((r)[2]), "=r"((r)[3]) : "r"(addr))

#define MMA_BF16(d, a, b) \
    asm volatile("mma.sync.aligned.m16n8k16.row.col.f32.bf16.bf16.f32 " \
        "{%0,%1,%2,%3}, {%4,%5,%6,%7}, {%8,%9}, {%0,%1,%2,%3};" \
        : "+f"((d)[0]), "+f"((d)[1]), "+f"((d)[2]), "+f"((d)[3]) \
        : "r"((a)[0]), "r"((a)[1]), "r"((a)[2]), "r"((a)[3]), \
          "r"((b)[0]), "r"((b)[1]))

// ===================== K1: contexts -> pooled vector v =====================
// One block per function b. 128 threads = one e-lane each.
__global__ void __launch_bounds__(128)
context_kernel(const int* __restrict__ v1i, const int* __restrict__ pthi,
               const int* __restrict__ v2i,
               const float* __restrict__ vemb, const float* __restrict__ pemb,
               const float* __restrict__ Wfc,  const float* __restrict__ bfc,
               const float* __restrict__ watt, const float* __restrict__ batt)
{
    __shared__ __align__(16) float ctx[NCTX][3 * EMB];   // 10 x 384
    __shared__ float s_logit[NCTX];

    int b = blockIdx.x;
    int tid = threadIdx.x;
    int wid = tid >> 5, lid = tid & 31;

    // Gather embeddings
    #pragma unroll
    for (int n = 0; n < NCTX; n++) {
        int i1 = v1i[b * NCTX + n];
        int ip = pthi[b * NCTX + n];
        int i2 = v2i[b * NCTX + n];
        ctx[n][tid]           = vemb[i1 * EMB + tid];
        ctx[n][EMB + tid]     = pemb[ip * EMB + tid];
        ctx[n][2 * EMB + tid] = vemb[i2 * EMB + tid];
    }
    __syncthreads();

    // c_tilde[n][tid] = tanh(b + sum_k ctx[n][k] * W[k][tid])
    float acc[NCTX];
    float bias = bfc[tid];
    #pragma unroll
    for (int n = 0; n < NCTX; n++) acc[n] = bias;

    for (int k4 = 0; k4 < 3 * EMB; k4 += 4) {
        float w0 = Wfc[(k4 + 0) * EMB + tid];
        float w1 = Wfc[(k4 + 1) * EMB + tid];
        float w2 = Wfc[(k4 + 2) * EMB + tid];
        float w3 = Wfc[(k4 + 3) * EMB + tid];
        #pragma unroll
        for (int n = 0; n < NCTX; n++) {
            float4 c = *reinterpret_cast<const float4*>(&ctx[n][k4]);
            acc[n] = fmaf(c.x, w0, acc[n]);
            acc[n] = fmaf(c.y, w1, acc[n]);
            acc[n] = fmaf(c.z, w2, acc[n]);
            acc[n] = fmaf(c.w, w3, acc[n]);
        }
    }
    #pragma unroll
    for (int n = 0; n < NCTX; n++) acc[n] = tanhf(acc[n]);

    // Attention logits: s[n] = sum_e c_tilde[n][e] * w_att[e]  (+ b_att later)
    float wa = watt[tid];
    float* cts = &ctx[0][0];   // reuse smem: 10*128 floats
    __syncthreads();
    #pragma unroll
    for (int n = 0; n < NCTX; n++) cts[n * EMB + tid] = acc[n] * wa;
    __syncthreads();
    for (int n = wid; n < NCTX; n += 4) {
        float p = cts[n * EMB + lid] + cts[n * EMB + lid + 32]
                + cts[n * EMB + lid + 64] + cts[n * EMB + lid + 96];
        #pragma unroll
        for (int o = 16; o > 0; o >>= 1) p += __shfl_xor_sync(0xFFFFFFFFu, p, o);
        if (lid == 0) s_logit[n] = p;
    }
    __syncthreads();

    // Softmax over the 10 contexts (every thread redundantly)
    float ba = batt[0];
    float sl[NCTX], mx = -1e30f;
    #pragma unroll
    for (int n = 0; n < NCTX; n++) { sl[n] = s_logit[n] + ba; mx = fmaxf(mx, sl[n]); }
    float ssum = 0.0f;
    #pragma unroll
    for (int n = 0; n < NCTX; n++) { sl[n] = expf(sl[n] - mx); ssum += sl[n]; }
    float rs = 1.0f / ssum;

    float vout = 0.0f;
    #pragma unroll
    for (int n = 0; n < NCTX; n++) vout = fmaf(acc[n], sl[n] * rs, vout);

    g_v_bf16[b * EMB + tid] = __float2bfloat16(vout);
}

// ===================== K2: tag_emb f32 -> bf16 =============================
__global__ void convert_tag_kernel(const float* __restrict__ tag) {
    int i = blockIdx.x * blockDim.x + threadIdx.x;
    int n4 = (VTAGS * EMB) / 4;    // 1,608,224 (exactly divisible)
    if (i < n4) {
        float4 v = reinterpret_cast<const float4*>(tag)[i];
        __nv_bfloat162 a, b;
        a.x = __float2bfloat16(v.x); a.y = __float2bfloat16(v.y);
        b.x = __float2bfloat16(v.z); b.y = __float2bfloat16(v.w);
        uint2 u;
        u.x = *reinterpret_cast<uint32_t*>(&a);
        u.y = *reinterpret_cast<uint32_t*>(&b);
        reinterpret_cast<uint2*>(g_tag_bf16)[i] = u;
    }
}

// ===================== K3: HMMA GEMM + softmax passes ======================
// Tile 128x128x128 bf16 via mma.sync.m16n8k16. 8 warps in 4(M) x 2(N) grid;
// each warp computes 32 rows x 64 cols = 2 m-atoms x 8 n-atoms.
// SMEM rows padded to 272B (conflict-free ldmatrix: 68 words % 32 = 4).
// Pass A (WRITE=false): per-row partial sum of exp(logit).
// Pass B (WRITE=true):  q = exp(logit) * inv_sum, direct sector-covering STG.
#define SA_STRIDE 272
#define SMEM_K3_TOTAL (2 * 128 * SA_STRIDE)   // 69632 B

template<bool WRITE>
__global__ void __launch_bounds__(256, 2)
gemm_softmax_kernel(float* __restrict__ out)
{
    extern __shared__ __align__(16) char smem[];
    char* sA = smem;                          // [128][272B] bf16 rows of A (v)
    char* sB = smem + 128 * SA_STRIDE;        // [128][272B] bf16 rows of B (tags)

    const int tid  = threadIdx.x;
    const int lane = tid & 31;
    const int wid  = tid >> 5;
    const int warp_m = wid & 3;               // * 32 rows
    const int warp_n = wid >> 2;              // * 64 cols
    const int tile_n0 = blockIdx.x * 128;
    const int tile_m0 = blockIdx.y * 128;

    // ---- Stage A tile (contiguous 32KB) ----
    const uint4* gA = reinterpret_cast<const uint4*>(g_v_bf16 + (size_t)tile_m0 * EMB);
    #pragma unroll
    for (int i = 0; i < 8; i++) {
        int j = tid + i * 256;                // 0..2047
        int row = j >> 4, c = j & 15;
        *reinterpret_cast<uint4*>(sA + row * SA_STRIDE + c * 16) = gA[j];
    }
    // ---- Stage B tile (bounds-checked rows) ----
    #pragma unroll
    for (int i = 0; i < 8; i++) {
        int j = tid + i * 256;
        int row = j >> 4, c = j & 15;
        int gr = tile_n0 + row;
        uint4 v = make_uint4(0u, 0u, 0u, 0u);
        if (gr < VTAGS)
            v = *reinterpret_cast<const uint4*>(g_tag_bf16 + (size_t)gr * EMB + c * 8);
        *reinterpret_cast<uint4*>(sB + row * SA_STRIDE + c * 16) = v;
    }
    __syncthreads();

    const uint32_t sA_u = smem_to_u32(sA);
    const uint32_t sB_u = smem_to_u32(sB);

    float acc[2][8][4];
    #pragma unroll
    for (int mi = 0; mi < 2; mi++)
        #pragma unroll
        for (int ni = 0; ni < 8; ni++)
            #pragma unroll
            for (int j = 0; j < 4; j++) acc[mi][ni][j] = 0.0f;

    // Per-lane ldmatrix base addresses.
    // A (x4 -> 16x16): lanes 0-7 rows 0-7 k0 | 8-15 rows 8-15 k0 |
    //                  16-23 rows 0-7 k8 | 24-31 rows 8-15 k8
    const uint32_t aAddr0 = sA_u + (warp_m * 32 + (lane & 15)) * SA_STRIDE
                                 + (lane >> 4) * 16;
    const uint32_t aAddr1 = aAddr0 + 16 * SA_STRIDE;
    // B (x4 -> two n8k16 frags): grp = lane>>3:
    //   g0: n+idx k0 | g1: n+idx k8 | g2: n+8+idx k0 | g3: n+8+idx k8
    const uint32_t bAddr = sB_u
        + (warp_n * 64 + (lane & 7) + ((lane >> 4) & 1) * 8) * SA_STRIDE
        + ((lane >> 3) & 1) * 16;

    #pragma unroll
    for (int ks = 0; ks < 8; ks++) {
        uint32_t a0[4], a1[4];
        LDMATRIX_X4(a0, aAddr0 + ks * 32);
        LDMATRIX_X4(a1, aAddr1 + ks * 32);
        uint32_t b[8][2];
        #pragma unroll
        for (int nb = 0; nb < 4; nb++) {
            uint32_t r[4];
            LDMATRIX_X4(r, bAddr + nb * 16 * SA_STRIDE + ks * 32);
            b[2 * nb][0]     = r[0]; b[2 * nb][1]     = r[1];
            b[2 * nb + 1][0] = r[2]; b[2 * nb + 1][1] = r[3];
        }
        #pragma unroll
        for (int ni = 0; ni < 8; ni++) {
            MMA_BF16(acc[0][ni], a0, b[ni]);
            MMA_BF16(acc[1][ni], a1, b[ni]);
        }
    }
    __syncthreads();   // smem reads done (pass A reuses smem below)

    // Accumulator ownership: rows r0 + {0,8,16,24}, r0 = warp_m*32 + lane>>2.
    // acc[mi][ni][{0,1}] -> row r0+mi*16,   cols nbase+{0,1}
    // acc[mi][ni][{2,3}] -> row r0+mi*16+8, cols nbase+{0,1}
    // nbase = warp_n*64 + ni*8 + 2*(lane&3)
    const int r0 = warp_m * 32 + (lane >> 2);
    const bool tail = (tile_n0 + 128 > VTAGS);

    if (!WRITE) {
        float s[4] = {0.0f, 0.0f, 0.0f, 0.0f};
        #pragma unroll
        for (int ni = 0; ni < 8; ni++) {
            int nb = tile_n0 + warp_n * 64 + ni * 8 + 2 * (lane & 3);
            #pragma unroll
            for (int j = 0; j < 2; j++) {
                if (!tail || (nb + j) < VTAGS) {
                    s[0] += __expf(acc[0][ni][j]);
                    s[1] += __expf(acc[0][ni][2 + j]);
                    s[2] += __expf(acc[1][ni][j]);
                    s[3] += __expf(acc[1][ni][2 + j]);
                }
            }
        }
        // quad reduce (lanes sharing a row differ only in lane&3)
        #pragma unroll
        for (int o = 1; o <= 2; o <<= 1) {
            #pragma unroll
            for (int k = 0; k < 4; k++)
                s[k] += __shfl_xor_sync(0xFFFFFFFFu, s[k], o);
        }
        float* red = reinterpret_cast<float*>(smem);   // [128][2]
        if ((lane & 3) == 0) {
            #pragma unroll
            for (int k = 0; k < 4; k++)
                red[(r0 + k * 8) * 2 + warp_n] = s[k];
        }
        __syncthreads();
        if (tid < 128)
            g_partials[(size_t)blockIdx.x * BATCH + tile_m0 + tid]
                = red[tid * 2] + red[tid * 2 + 1];
    } else {
        float inv[4];
        #pragma unroll
        for (int k = 0; k < 4; k++)
            inv[k] = g_inv_sum[tile_m0 + r0 + k * 8];
        #pragma unroll
        for (int ni = 0; ni < 8; ni++) {
            int nb = tile_n0 + warp_n * 64 + ni * 8 + 2 * (lane & 3);
            #pragma unroll
            for (int k = 0; k < 4; k++) {
                int mi = k >> 1, jo = (k & 1) * 2;
                int m = tile_m0 + r0 + k * 8;
                float v0 = __expf(acc[mi][ni][jo + 0]) * inv[k];
                float v1 = __expf(acc[mi][ni][jo + 1]) * inv[k];
                float* p = out + (size_t)m * VTAGS + nb;
                if (!tail || (nb + 1) < VTAGS) {
                    stg_cs(p, v0);
                    stg_cs(p + 1, v1);
                } else if (nb < VTAGS) {
                    stg_cs(p, v0);
                }
            }
        }
    }
}

// ===================== K4: deterministic reduce of partials =================
__global__ void reduce_kernel() {
    int m = blockIdx.x * blockDim.x + threadIdx.x;
    if (m < BATCH) {
        float s = 0.0f;
        for (int t = 0; t < NTILES; t++) s += g_partials[t * BATCH + m];
        g_inv_sum[m] = 1.0f / s;
    }
}

// ============================ launch ======================================
extern "C" void kernel_launch(void* const* d_in, const int* in_sizes, int n_in,
                              void* d_out, int out_size)
{
    const int*   v1i  = (const int*)d_in[0];
    const int*   pthi = (const int*)d_in[1];
    const int*   v2i  = (const int*)d_in[2];
    const float* vemb = (const float*)d_in[3];
    const float* pemb = (const float*)d_in[4];
    const float* temb = (const float*)d_in[5];
    const float* Wfc  = (const float*)d_in[6];
    const float* bfc  = (const float*)d_in[7];
    const float* watt = (const float*)d_in[8];
    const float* batt = (const float*)d_in[9];
    float* out = (float*)d_out;

    cudaFuncSetAttribute(gemm_softmax_kernel<false>,
                         cudaFuncAttributeMaxDynamicSharedMemorySize, SMEM_K3_TOTAL);
    cudaFuncSetAttribute(gemm_softmax_kernel<true>,
                         cudaFuncAttributeMaxDynamicSharedMemorySize, SMEM_K3_TOTAL);

    context_kernel<<<BATCH, 128>>>(v1i, pthi, v2i, vemb, pemb, Wfc, bfc, watt, batt);

    int n4 = (VTAGS * EMB) / 4;
    convert_tag_kernel<<<(n4 + 255) / 256, 256>>>(temb);

    dim3 grid(NTILES, BATCH / 128);
    gemm_softmax_kernel<false><<<grid, 256, SMEM_K3_TOTAL>>>(nullptr);
    reduce_kernel<<<BATCH / 256, 256>>>();
    gemm_softmax_kernel<true><<<grid, 256, SMEM_K3_TOTAL>>>(out);
}

// round 8
// speedup vs baseline: 1.0145x; 1.0145x over previous
#include <cuda_runtime.h>
#include <cuda_bf16.h>
#include <cstdint>

// ============================ Problem constants ============================
#define VTAGS 50257
#define BATCH 2048
#define EMB   128
#define NCTX  10
#define NTILES 393            // ceil(50257/128)

// ============================ Scratch (device globals) =====================
__device__ __nv_bfloat16 g_v_bf16[BATCH * EMB];            // pooled code vectors, bf16
__device__ __nv_bfloat16 g_tag_bf16[VTAGS * EMB];          // tag embedding, bf16
__device__ float g_partials[NTILES * BATCH];               // per (ntile, row) sumexp
__device__ float g_inv_sum[BATCH];                         // 1 / sumexp per row

// ============================ helpers ======================================
__device__ __forceinline__ uint32_t smem_to_u32(const void* smem_ptr) {
    uint32_t addr;
    asm("{ .reg .u64 tmp; cvta.to.shared.u64 tmp, %1; cvt.u32.u64 %0, tmp; }"
        : "=r"(addr) : "l"(smem_ptr));
    return addr;
}

// streaming store (evict-first): keep L2 for the bf16 tag matrix
__device__ __forceinline__ void stg_cs(float* p, float v) {
    asm volatile("st.global.cs.f32 [%0], %1;" :: "l"(p), "f"(v) : "memory");
}

#define LDMATRIX_X4(r, addr) \
    asm volatile("ldmatrix.sync.aligned.m8n8.x4.shared.b16 {%0,%1,%2,%3}, [%4];" \
        : "=r"((r)[0]), "=r"((r)[1]), "=r"((r)[2]), "=r"((r)[3]) : "r"(addr))

#define MMA_BF16(d, a, b) \
    asm volatile("mma.sync.aligned.m16n8k16.row.col.f32.bf16.bf16.f32 " \
        "{%0,%1,%2,%3}, {%4,%5,%6,%7}, {%8,%9}, {%0,%1,%2,%3};" \
        : "+f"((d)[0]), "+f"((d)[1]), "+f"((d)[2]), "+f"((d)[3]) \
        : "r"((a)[0]), "r"((a)[1]), "r"((a)[2]), "r"((a)[3]), \
          "r"((b)[0]), "r"((b)[1]))

// ===================== K1: contexts -> pooled vector v (+ tag convert) =====
// One block per function b. 128 threads = one e-lane each.
// Tail: grid-stride conversion of tag_emb f32 -> bf16 (fused, independent).
__global__ void __launch_bounds__(128)
context_kernel(const int* __restrict__ v1i, const int* __restrict__ pthi,
               const int* __restrict__ v2i,
               const float* __restrict__ vemb, const float* __restrict__ pemb,
               const float* __restrict__ tag,
               const float* __restrict__ Wfc,  const float* __restrict__ bfc,
               const float* __restrict__ watt, const float* __restrict__ batt)
{
    __shared__ __align__(16) float ctx[NCTX][3 * EMB];   // 10 x 384
    __shared__ float s_logit[NCTX];

    int b = blockIdx.x;
    int tid = threadIdx.x;
    int wid = tid >> 5, lid = tid & 31;

    // ---- Fused tag conversion (independent of the rest; overlaps gathers) ----
    {
        const int n4 = (VTAGS * EMB) / 4;        // 1,608,224 float4 groups
        const int nthreads = BATCH * 128;        // 262,144
        for (int i = b * 128 + tid; i < n4; i += nthreads) {
            float4 v = reinterpret_cast<const float4*>(tag)[i];
            __nv_bfloat162 a2, b2;
            a2.x = __float2bfloat16(v.x); a2.y = __float2bfloat16(v.y);
            b2.x = __float2bfloat16(v.z); b2.y = __float2bfloat16(v.w);
            uint2 u;
            u.x = *reinterpret_cast<uint32_t*>(&a2);
            u.y = *reinterpret_cast<uint32_t*>(&b2);
            reinterpret_cast<uint2*>(g_tag_bf16)[i] = u;
        }
    }

    // ---- Gather embeddings ----
    #pragma unroll
    for (int n = 0; n < NCTX; n++) {
        int i1 = v1i[b * NCTX + n];
        int ip = pthi[b * NCTX + n];
        int i2 = v2i[b * NCTX + n];
        ctx[n][tid]           = vemb[i1 * EMB + tid];
        ctx[n][EMB + tid]     = pemb[ip * EMB + tid];
        ctx[n][2 * EMB + tid] = vemb[i2 * EMB + tid];
    }
    __syncthreads();

    // c_tilde[n][tid] = tanh(b + sum_k ctx[n][k] * W[k][tid])
    float acc[NCTX];
    float bias = bfc[tid];
    #pragma unroll
    for (int n = 0; n < NCTX; n++) acc[n] = bias;

    for (int k4 = 0; k4 < 3 * EMB; k4 += 4) {
        float w0 = Wfc[(k4 + 0) * EMB + tid];
        float w1 = Wfc[(k4 + 1) * EMB + tid];
        float w2 = Wfc[(k4 + 2) * EMB + tid];
        float w3 = Wfc[(k4 + 3) * EMB + tid];
        #pragma unroll
        for (int n = 0; n < NCTX; n++) {
            float4 c = *reinterpret_cast<const float4*>(&ctx[n][k4]);
            acc[n] = fmaf(c.x, w0, acc[n]);
            acc[n] = fmaf(c.y, w1, acc[n]);
            acc[n] = fmaf(c.z, w2, acc[n]);
            acc[n] = fmaf(c.w, w3, acc[n]);
        }
    }
    #pragma unroll
    for (int n = 0; n < NCTX; n++) acc[n] = tanhf(acc[n]);

    // Attention logits: s[n] = sum_e c_tilde[n][e] * w_att[e]  (+ b_att later)
    float wa = watt[tid];
    float* cts = &ctx[0][0];   // reuse smem: 10*128 floats
    __syncthreads();
    #pragma unroll
    for (int n = 0; n < NCTX; n++) cts[n * EMB + tid] = acc[n] * wa;
    __syncthreads();
    for (int n = wid; n < NCTX; n += 4) {
        float p = cts[n * EMB + lid] + cts[n * EMB + lid + 32]
                + cts[n * EMB + lid + 64] + cts[n * EMB + lid + 96];
        #pragma unroll
        for (int o = 16; o > 0; o >>= 1) p += __shfl_xor_sync(0xFFFFFFFFu, p, o);
        if (lid == 0) s_logit[n] = p;
    }
    __syncthreads();

    // Softmax over the 10 contexts (every thread redundantly)
    float ba = batt[0];
    float sl[NCTX], mx = -1e30f;
    #pragma unroll
    for (int n = 0; n < NCTX; n++) { sl[n] = s_logit[n] + ba; mx = fmaxf(mx, sl[n]); }
    float ssum = 0.0f;
    #pragma unroll
    for (int n = 0; n < NCTX; n++) { sl[n] = expf(sl[n] - mx); ssum += sl[n]; }
    float rs = 1.0f / ssum;

    float vout = 0.0f;
    #pragma unroll
    for (int n = 0; n < NCTX; n++) vout = fmaf(acc[n], sl[n] * rs, vout);

    g_v_bf16[b * EMB + tid] = __float2bfloat16(vout);
}

// ===================== K3: HMMA GEMM + softmax passes ======================
// Tile 128x128x128 bf16 via mma.sync.m16n8k16. 8 warps in 4(M) x 2(N) grid;
// each warp computes 32 rows x 64 cols = 2 m-atoms x 8 n-atoms.
// SMEM rows padded to 272B (conflict-free ldmatrix: 68 words % 32 = 4).
// Pass A (WRITE=false): per-row partial sum of exp(logit).
// Pass B (WRITE=true):  q = exp(logit) * inv_sum, direct sector-covering STG.
#define SA_STRIDE 272
#define SMEM_K3_TOTAL (2 * 128 * SA_STRIDE)   // 69632 B

template<bool WRITE>
__global__ void __launch_bounds__(256, 2)
gemm_softmax_kernel(float* __restrict__ out)
{
    extern __shared__ __align__(16) char smem[];
    char* sA = smem;                          // [128][272B] bf16 rows of A (v)
    char* sB = smem + 128 * SA_STRIDE;        // [128][272B] bf16 rows of B (tags)

    const int tid  = threadIdx.x;
    const int lane = tid & 31;
    const int wid  = tid >> 5;
    const int warp_m = wid & 3;               // * 32 rows
    const int warp_n = wid >> 2;              // * 64 cols
    const int tile_n0 = blockIdx.x * 128;
    const int tile_m0 = blockIdx.y * 128;

    // ---- Stage A tile (contiguous 32KB) ----
    const uint4* gA = reinterpret_cast<const uint4*>(g_v_bf16 + (size_t)tile_m0 * EMB);
    #pragma unroll
    for (int i = 0; i < 8; i++) {
        int j = tid + i * 256;                // 0..2047
        int row = j >> 4, c = j & 15;
        *reinterpret_cast<uint4*>(sA + row * SA_STRIDE + c * 16) = gA[j];
    }
    // ---- Stage B tile (bounds-checked rows) ----
    #pragma unroll
    for (int i = 0; i < 8; i++) {
        int j = tid + i * 256;
        int row = j >> 4, c = j & 15;
        int gr = tile_n0 + row;
        uint4 v = make_uint4(0u, 0u, 0u, 0u);
        if (gr < VTAGS)
            v = *reinterpret_cast<const uint4*>(g_tag_bf16 + (size_t)gr * EMB + c * 8);
        *reinterpret_cast<uint4*>(sB + row * SA_STRIDE + c * 16) = v;
    }
    __syncthreads();

    const uint32_t sA_u = smem_to_u32(sA);
    const uint32_t sB_u = smem_to_u32(sB);

    float acc[2][8][4];
    #pragma unroll
    for (int mi = 0; mi < 2; mi++)
        #pragma unroll
        for (int ni = 0; ni < 8; ni++)
            #pragma unroll
            for (int j = 0; j < 4; j++) acc[mi][ni][j] = 0.0f;

    // Per-lane ldmatrix base addresses.
    // A (x4 -> 16x16): lanes 0-7 rows 0-7 k0 | 8-15 rows 8-15 k0 |
    //                  16-23 rows 0-7 k8 | 24-31 rows 8-15 k8
    const uint32_t aAddr0 = sA_u + (warp_m * 32 + (lane & 15)) * SA_STRIDE
                                 + (lane >> 4) * 16;
    const uint32_t aAddr1 = aAddr0 + 16 * SA_STRIDE;
    // B (x4 -> two n8k16 frags): grp = lane>>3:
    //   g0: n+idx k0 | g1: n+idx k8 | g2: n+8+idx k0 | g3: n+8+idx k8
    const uint32_t bAddr = sB_u
        + (warp_n * 64 + (lane & 7) + ((lane >> 4) & 1) * 8) * SA_STRIDE
        + ((lane >> 3) & 1) * 16;

    #pragma unroll
    for (int ks = 0; ks < 8; ks++) {
        uint32_t a0[4], a1[4];
        LDMATRIX_X4(a0, aAddr0 + ks * 32);
        LDMATRIX_X4(a1, aAddr1 + ks * 32);
        uint32_t b[8][2];
        #pragma unroll
        for (int nb = 0; nb < 4; nb++) {
            uint32_t r[4];
            LDMATRIX_X4(r, bAddr + nb * 16 * SA_STRIDE + ks * 32);
            b[2 * nb][0]     = r[0]; b[2 * nb][1]     = r[1];
            b[2 * nb + 1][0] = r[2]; b[2 * nb + 1][1] = r[3];
        }
        #pragma unroll
        for (int ni = 0; ni < 8; ni++) {
            MMA_BF16(acc[0][ni], a0, b[ni]);
            MMA_BF16(acc[1][ni], a1, b[ni]);
        }
    }
    __syncthreads();   // smem reads done (pass A reuses smem below)

    // Accumulator ownership: rows r0 + {0,8,16,24}, r0 = warp_m*32 + lane>>2.
    // acc[mi][ni][{0,1}] -> row r0+mi*16,   cols nbase+{0,1}
    // acc[mi][ni][{2,3}] -> row r0+mi*16+8, cols nbase+{0,1}
    // nbase = warp_n*64 + ni*8 + 2*(lane&3)
    const int r0 = warp_m * 32 + (lane >> 2);
    const bool tail = (tile_n0 + 128 > VTAGS);

    if (!WRITE) {
        float s[4] = {0.0f, 0.0f, 0.0f, 0.0f};
        #pragma unroll
        for (int ni = 0; ni < 8; ni++) {
            int nb = tile_n0 + warp_n * 64 + ni * 8 + 2 * (lane & 3);
            #pragma unroll
            for (int j = 0; j < 2; j++) {
                if (!tail || (nb + j) < VTAGS) {
                    s[0] += __expf(acc[0][ni][j]);
                    s[1] += __expf(acc[0][ni][2 + j]);
                    s[2] += __expf(acc[1][ni][j]);
                    s[3] += __expf(acc[1][ni][2 + j]);
                }
            }
        }
        // quad reduce (lanes sharing a row differ only in lane&3)
        #pragma unroll
        for (int o = 1; o <= 2; o <<= 1) {
            #pragma unroll
            for (int k = 0; k < 4; k++)
                s[k] += __shfl_xor_sync(0xFFFFFFFFu, s[k], o);
        }
        float* red = reinterpret_cast<float*>(smem);   // [128][2]
        if ((lane & 3) == 0) {
            #pragma unroll
            for (int k = 0; k < 4; k++)
                red[(r0 + k * 8) * 2 + warp_n] = s[k];
        }
        __syncthreads();
        if (tid < 128)
            g_partials[(size_t)blockIdx.x * BATCH + tile_m0 + tid]
                = red[tid * 2] + red[tid * 2 + 1];
    } else {
        float inv[4];
        #pragma unroll
        for (int k = 0; k < 4; k++)
            inv[k] = g_inv_sum[tile_m0 + r0 + k * 8];
        #pragma unroll
        for (int ni = 0; ni < 8; ni++) {
            int nb = tile_n0 + warp_n * 64 + ni * 8 + 2 * (lane & 3);
            #pragma unroll
            for (int k = 0; k < 4; k++) {
                int mi = k >> 1, jo = (k & 1) * 2;
                int m = tile_m0 + r0 + k * 8;
                float v0 = __expf(acc[mi][ni][jo + 0]) * inv[k];
                float v1 = __expf(acc[mi][ni][jo + 1]) * inv[k];
                float* p = out + (size_t)m * VTAGS + nb;
                if (!tail || (nb + 1) < VTAGS) {
                    stg_cs(p, v0);
                    stg_cs(p + 1, v1);
                } else if (nb < VTAGS) {
                    stg_cs(p, v0);
                }
            }
        }
    }
}

// ===================== K4: deterministic reduce of partials =================
// One warp per batch row; lanes stride the 393 tiles, then shfl-tree reduce.
__global__ void __launch_bounds__(256)
reduce_kernel() {
    int m = blockIdx.x * 8 + (threadIdx.x >> 5);
    int lane = threadIdx.x & 31;
    float s = 0.0f;
    for (int t = lane; t < NTILES; t += 32)
        s += g_partials[(size_t)t * BATCH + m];
    #pragma unroll
    for (int o = 16; o > 0; o >>= 1) s += __shfl_xor_sync(0xFFFFFFFFu, s, o);
    if (lane == 0) g_inv_sum[m] = 1.0f / s;
}

// ============================ launch ======================================
extern "C" void kernel_launch(void* const* d_in, const int* in_sizes, int n_in,
                              void* d_out, int out_size)
{
    const int*   v1i  = (const int*)d_in[0];
    const int*   pthi = (const int*)d_in[1];
    const int*   v2i  = (const int*)d_in[2];
    const float* vemb = (const float*)d_in[3];
    const float* pemb = (const float*)d_in[4];
    const float* temb = (const float*)d_in[5];
    const float* Wfc  = (const float*)d_in[6];
    const float* bfc  = (const float*)d_in[7];
    const float* watt = (const float*)d_in[8];
    const float* batt = (const float*)d_in[9];
    float* out = (float*)d_out;

    cudaFuncSetAttribute(gemm_softmax_kernel<false>,
                         cudaFuncAttributeMaxDynamicSharedMemorySize, SMEM_K3_TOTAL);
    cudaFuncSetAttribute(gemm_softmax_kernel<true>,
                         cudaFuncAttributeMaxDynamicSharedMemorySize, SMEM_K3_TOTAL);

    // Launch order matters for profiling: ncu captures the 4th launch -> gemmB.
    context_kernel<<<BATCH, 128>>>(v1i, pthi, v2i, vemb, pemb, temb,
                                   Wfc, bfc, watt, batt);

    dim3 grid(NTILES, BATCH / 128);
    gemm_softmax_kernel<false><<<grid, 256, SMEM_K3_TOTAL>>>(nullptr);
    reduce_kernel<<<BATCH / 8, 256>>>();
    gemm_softmax_kernel<true><<<grid, 256, SMEM_K3_TOTAL>>>(out);
}

// round 11
// speedup vs baseline: 1.5293x; 1.5074x over previous
#include <cuda_runtime.h>
#include <cuda_bf16.h>
#include <cstdint>

// ============================ Problem constants ============================
#define VTAGS 50257
#define BATCH 2048
#define EMB   128
#define NCTX  10
#define NT      4             // n-tiles per CTA
#define NGROUPS 99            // ceil(393 / NT)

// ============================ Scratch (device globals) =====================
__device__ __nv_bfloat16 g_v_bf16[BATCH * EMB];            // pooled code vectors, bf16
__device__ __nv_bfloat16 g_tag_bf16[VTAGS * EMB];          // tag embedding, bf16
__device__ float g_partials[NGROUPS * BATCH];              // per (group, row) sumexp
__device__ float g_inv_sum[BATCH];                         // 1 / sumexp per row

// ============================ helpers ======================================
__device__ __forceinline__ uint32_t smem_to_u32(const void* smem_ptr) {
    uint32_t addr;
    asm("{ .reg .u64 tmp; cvta.to.shared.u64 tmp, %1; cvt.u32.u64 %0, tmp; }"
        : "=r"(addr) : "l"(smem_ptr));
    return addr;
}

// streaming store (evict-first): keep L2 for the bf16 tag matrix
__device__ __forceinline__ void stg_cs(float* p, float v) {
    asm volatile("st.global.cs.f32 [%0], %1;" :: "l"(p), "f"(v) : "memory");
}

__device__ __forceinline__ void cp_async16(uint32_t dst, const void* src) {
    asm volatile("cp.async.cg.shared.global [%0], [%1], 16;"
                 :: "r"(dst), "l"(src) : "memory");
}
__device__ __forceinline__ void cp_commit() {
    asm volatile("cp.async.commit_group;" ::: "memory");
}
__device__ __forceinline__ void cp_wait1() {
    asm volatile("cp.async.wait_group 1;" ::: "memory");
}
__device__ __forceinline__ void cp_wait0() {
    asm volatile("cp.async.wait_group 0;" ::: "memory");
}

#define LDMATRIX_X4(r, addr) \
    asm volatile("ldmatrix.sync.aligned.m8n8.x4.shared.b16 {%0,%1,%2,%3}, [%4];" \
        : "=r"((r)[0]), "=r"((r)[1]), "=r"((r)[2]), "=r"((r)[3]) : "r"(addr))

#define MMA_BF16(d, a, b) \
    asm volatile("mma.sync.aligned.m16n8k16.row.col.f32.bf16.bf16.f32 " \
        "{%0,%1,%2,%3}, {%4,%5,%6,%7}, {%8,%9}, {%0,%1,%2,%3};" \
        : "+f"((d)[0]), "+f"((d)[1]), "+f"((d)[2]), "+f"((d)[3]) \
        : "r"((a)[0]), "r"((a)[1]), "r"((a)[2]), "r"((a)[3]), \
          "r"((b)[0]), "r"((b)[1]))

// ===================== K1: contexts -> pooled vector v (+ tag convert) =====
__global__ void __launch_bounds__(128)
context_kernel(const int* __restrict__ v1i, const int* __restrict__ pthi,
               const int* __restrict__ v2i,
               const float* __restrict__ vemb, const float* __restrict__ pemb,
               const float* __restrict__ tag,
               const float* __restrict__ Wfc,  const float* __restrict__ bfc,
               const float* __restrict__ watt, const float* __restrict__ batt)
{
    __shared__ __align__(16) float ctx[NCTX][3 * EMB];   // 10 x 384
    __shared__ float s_logit[NCTX];

    int b = blockIdx.x;
    int tid = threadIdx.x;
    int wid = tid >> 5, lid = tid & 31;

    // ---- Fused tag conversion (independent work; overlaps gathers) ----
    {
        const int n4 = (VTAGS * EMB) / 4;        // 1,608,224 float4 groups
        const int nthreads = BATCH * 128;        // 262,144
        for (int i = b * 128 + tid; i < n4; i += nthreads) {
            float4 v = reinterpret_cast<const float4*>(tag)[i];
            __nv_bfloat162 a2, b2;
            a2.x = __float2bfloat16(v.x); a2.y = __float2bfloat16(v.y);
            b2.x = __float2bfloat16(v.z); b2.y = __float2bfloat16(v.w);
            uint2 u;
            u.x = *reinterpret_cast<uint32_t*>(&a2);
            u.y = *reinterpret_cast<uint32_t*>(&b2);
            reinterpret_cast<uint2*>(g_tag_bf16)[i] = u;
        }
    }

    // ---- Gather embeddings ----
    #pragma unroll
    for (int n = 0; n < NCTX; n++) {
        int i1 = v1i[b * NCTX + n];
        int ip = pthi[b * NCTX + n];
        int i2 = v2i[b * NCTX + n];
        ctx[n][tid]           = vemb[i1 * EMB + tid];
        ctx[n][EMB + tid]     = pemb[ip * EMB + tid];
        ctx[n][2 * EMB + tid] = vemb[i2 * EMB + tid];
    }
    __syncthreads();

    float acc[NCTX];
    float bias = bfc[tid];
    #pragma unroll
    for (int n = 0; n < NCTX; n++) acc[n] = bias;

    for (int k4 = 0; k4 < 3 * EMB; k4 += 4) {
        float w0 = Wfc[(k4 + 0) * EMB + tid];
        float w1 = Wfc[(k4 + 1) * EMB + tid];
        float w2 = Wfc[(k4 + 2) * EMB + tid];
        float w3 = Wfc[(k4 + 3) * EMB + tid];
        #pragma unroll
        for (int n = 0; n < NCTX; n++) {
            float4 c = *reinterpret_cast<const float4*>(&ctx[n][k4]);
            acc[n] = fmaf(c.x, w0, acc[n]);
            acc[n] = fmaf(c.y, w1, acc[n]);
            acc[n] = fmaf(c.z, w2, acc[n]);
            acc[n] = fmaf(c.w, w3, acc[n]);
        }
    }
    #pragma unroll
    for (int n = 0; n < NCTX; n++) acc[n] = tanhf(acc[n]);

    float wa = watt[tid];
    float* cts = &ctx[0][0];
    __syncthreads();
    #pragma unroll
    for (int n = 0; n < NCTX; n++) cts[n * EMB + tid] = acc[n] * wa;
    __syncthreads();
    for (int n = wid; n < NCTX; n += 4) {
        float p = cts[n * EMB + lid] + cts[n * EMB + lid + 32]
                + cts[n * EMB + lid + 64] + cts[n * EMB + lid + 96];
        #pragma unroll
        for (int o = 16; o > 0; o >>= 1) p += __shfl_xor_sync(0xFFFFFFFFu, p, o);
        if (lid == 0) s_logit[n] = p;
    }
    __syncthreads();

    float ba = batt[0];
    float sl[NCTX], mx = -1e30f;
    #pragma unroll
    for (int n = 0; n < NCTX; n++) { sl[n] = s_logit[n] + ba; mx = fmaxf(mx, sl[n]); }
    float ssum = 0.0f;
    #pragma unroll
    for (int n = 0; n < NCTX; n++) { sl[n] = expf(sl[n] - mx); ssum += sl[n]; }
    float rs = 1.0f / ssum;

    float vout = 0.0f;
    #pragma unroll
    for (int n = 0; n < NCTX; n++) vout = fmaf(acc[n], sl[n] * rs, vout);

    g_v_bf16[b * EMB + tid] = __float2bfloat16(vout);
}

// ===================== K3: HMMA GEMM + softmax, NT tiles per CTA ===========
// Per CTA: stage A once; loop over NT n-tiles with double-buffered cp.async B.
// Pass A: accumulate sumexp across tiles -> one partial per (group, row).
// Pass B: q = exp*inv via smem-transposed, 128B-coalesced streaming stores.
#define SA_STRIDE 272
#define SMEM_A_OFF   0
#define SMEM_B_OFF   34816
#define SMEM_B_BYTES 34816
#define SMEM_RED_OFF (SMEM_B_OFF + 2 * SMEM_B_BYTES)   // 104448
#define SMEM_K3_TOTAL (SMEM_RED_OFF + 1024)            // 105472

template<bool WRITE>
__global__ void __launch_bounds__(256, 2)
gemm_softmax_kernel(float* __restrict__ out)
{
    extern __shared__ __align__(16) char smem[];

    const int tid  = threadIdx.x;
    const int lane = tid & 31;
    const int wid  = tid >> 5;
    const int warp_m = wid & 3;               // * 32 rows
    const int warp_n = wid >> 2;              // * 64 cols
    const int group_n0 = blockIdx.x * (NT * 128);
    const int tile_m0 = blockIdx.y * 128;

    const uint32_t smem_u = smem_to_u32(smem);
    const uint32_t sAu = smem_u + SMEM_A_OFF;

    // ---- Stage A tile (once per CTA) ----
    const uint4* gA = reinterpret_cast<const uint4*>(g_v_bf16 + (size_t)tile_m0 * EMB);
    #pragma unroll
    for (int i = 0; i < 8; i++) {
        int j = tid + i * 256;
        int row = j >> 4, c = j & 15;
        *reinterpret_cast<uint4*>(smem + SMEM_A_OFF + row * SA_STRIDE + c * 16) = gA[j];
    }

    // ---- B prefetch (cp.async, clamped rows; garbage rows masked later) ----
    auto issueB = [&](int t, int buf) {
        int n0 = group_n0 + t * 128;
        uint32_t base = smem_u + SMEM_B_OFF + buf * SMEM_B_BYTES;
        #pragma unroll
        for (int i = 0; i < 8; i++) {
            int j = tid + i * 256;
            int row = j >> 4, c16 = j & 15;
            int gr = n0 + row; if (gr > VTAGS - 1) gr = VTAGS - 1;
            cp_async16(base + row * SA_STRIDE + c16 * 16,
                       g_tag_bf16 + (size_t)gr * EMB + c16 * 8);
        }
        cp_commit();
    };
    issueB(0, 0);

    // Per-lane ldmatrix offsets (same fragment layout as before)
    const uint32_t aAddr0 = sAu + (warp_m * 32 + (lane & 15)) * SA_STRIDE
                                + (lane >> 4) * 16;
    const uint32_t aAddr1 = aAddr0 + 16 * SA_STRIDE;
    const uint32_t bOff = (warp_n * 64 + (lane & 7) + ((lane >> 4) & 1) * 8) * SA_STRIDE
                        + ((lane >> 3) & 1) * 16;

    const int r0 = warp_m * 32 + (lane >> 2);
    float ssum[4] = {0.0f, 0.0f, 0.0f, 0.0f};
    float inv[4];
    if (WRITE) {
        #pragma unroll
        for (int k = 0; k < 4; k++)
            inv[k] = g_inv_sum[tile_m0 + r0 + k * 8];
    }

    for (int t = 0; t < NT; t++) {
        const int buf = t & 1;
        const uint32_t sBu = smem_u + SMEM_B_OFF + buf * SMEM_B_BYTES;
        if (t + 1 < NT) { issueB(t + 1, buf ^ 1); cp_wait1(); }
        else           { cp_wait0(); }
        __syncthreads();          // A staged (t=0) + B[buf] visible to all

        float acc[2][8][4];
        #pragma unroll
        for (int mi = 0; mi < 2; mi++)
            #pragma unroll
            for (int ni = 0; ni < 8; ni++)
                #pragma unroll
                for (int j = 0; j < 4; j++) acc[mi][ni][j] = 0.0f;

        const uint32_t bAddr = sBu + bOff;
        #pragma unroll
        for (int ks = 0; ks < 8; ks++) {
            uint32_t a0[4], a1[4];
            LDMATRIX_X4(a0, aAddr0 + ks * 32);
            LDMATRIX_X4(a1, aAddr1 + ks * 32);
            uint32_t b[8][2];
            #pragma unroll
            for (int nb = 0; nb < 4; nb++) {
                uint32_t r[4];
                LDMATRIX_X4(r, bAddr + nb * 16 * SA_STRIDE + ks * 32);
                b[2 * nb][0]     = r[0]; b[2 * nb][1]     = r[1];
                b[2 * nb + 1][0] = r[2]; b[2 * nb + 1][1] = r[3];
            }
            #pragma unroll
            for (int ni = 0; ni < 8; ni++) {
                MMA_BF16(acc[0][ni], a0, b[ni]);
                MMA_BF16(acc[1][ni], a1, b[ni]);
            }
        }
        __syncthreads();          // all reads of B[buf] done

        const int tile_n0 = group_n0 + t * 128;
        const bool tail = (tile_n0 + 128 > VTAGS);

        if (!WRITE) {
            // accumulate sumexp across tiles (masked on tail/OOB tiles)
            #pragma unroll
            for (int ni = 0; ni < 8; ni++) {
                int nb = tile_n0 + warp_n * 64 + ni * 8 + 2 * (lane & 3);
                #pragma unroll
                for (int j = 0; j < 2; j++) {
                    if (!tail || (nb + j) < VTAGS) {
                        ssum[0] += __expf(acc[0][ni][j]);
                        ssum[1] += __expf(acc[0][ni][2 + j]);
                        ssum[2] += __expf(acc[1][ni][j]);
                        ssum[3] += __expf(acc[1][ni][2 + j]);
                    }
                }
            }
        } else {
            // Transposed staging in the just-consumed B buffer, then
            // 128B-coalesced streaming stores. Two 64-row halves.
            float* stage = reinterpret_cast<float*>(smem + SMEM_B_OFF
                                                    + buf * SMEM_B_BYTES);
            #pragma unroll
            for (int h = 0; h < 2; h++) {
                if ((warp_m >> 1) == h) {
                    const int wm = warp_m & 1;
                    #pragma unroll
                    for (int ni = 0; ni < 8; ni++) {
                        int c = warp_n * 64 + ni * 8 + 2 * (lane & 3);
                        #pragma unroll
                        for (int k = 0; k < 4; k++) {
                            int mi = k >> 1, jo = (k & 1) * 2;
                            int lr = wm * 32 + (lane >> 2) + 8 * k;
                            float v0 = __expf(acc[mi][ni][jo + 0]) * inv[k];
                            float v1 = __expf(acc[mi][ni][jo + 1]) * inv[k];
                            int cs = c ^ ((lr & 3) << 3);     // XOR swizzle
                            float2* p = reinterpret_cast<float2*>(stage + lr * 128 + cs);
                            *p = make_float2(v0, v1);
                        }
                    }
                }
                __syncthreads();    // staging visible
                #pragma unroll
                for (int it = 0; it < 8; it++) {
                    int row = it * 8 + wid;               // 0..63
                    int m = tile_m0 + h * 64 + row;
                    int sw = (row & 3) << 3;
                    #pragma unroll
                    for (int i = 0; i < 4; i++) {
                        int col = lane + 32 * i;
                        float v = stage[row * 128 + (col ^ sw)];
                        int gn = tile_n0 + col;
                        if (gn < VTAGS)
                            stg_cs(out + (size_t)m * VTAGS + gn, v);
                    }
                }
                __syncthreads();    // staging consumed (buffer reused next)
            }
        }
    }

    if (!WRITE) {
        // cross-warp_n reduce -> one partial per (group, row)
        #pragma unroll
        for (int o = 1; o <= 2; o <<= 1) {
            #pragma unroll
            for (int k = 0; k < 4; k++)
                ssum[k] += __shfl_xor_sync(0xFFFFFFFFu, ssum[k], o);
        }
        float* red = reinterpret_cast<float*>(smem + SMEM_RED_OFF);  // [128][2]
        if ((lane & 3) == 0) {
            #pragma unroll
            for (int k = 0; k < 4; k++)
                red[(r0 + k * 8) * 2 + warp_n] = ssum[k];
        }
        __syncthreads();
        if (tid < 128)
            g_partials[(size_t)blockIdx.x * BATCH + tile_m0 + tid]
                = red[tid * 2] + red[tid * 2 + 1];
    }
}

// ===================== K4: deterministic reduce of partials =================
// One warp per batch row; lanes stride the 99 groups, then shfl-tree reduce.
__global__ void __launch_bounds__(256)
reduce_kernel() {
    int m = blockIdx.x * 8 + (threadIdx.x >> 5);
    int lane = threadIdx.x & 31;
    float s = 0.0f;
    for (int t = lane; t < NGROUPS; t += 32)
        s += g_partials[(size_t)t * BATCH + m];
    #pragma unroll
    for (int o = 16; o > 0; o >>= 1) s += __shfl_xor_sync(0xFFFFFFFFu, s, o);
    if (lane == 0) g_inv_sum[m] = 1.0f / s;
}

// ============================ launch ======================================
extern "C" void kernel_launch(void* const* d_in, const int* in_sizes, int n_in,
                              void* d_out, int out_size)
{
    const int*   v1i  = (const int*)d_in[0];
    const int*   pthi = (const int*)d_in[1];
    const int*   v2i  = (const int*)d_in[2];
    const float* vemb = (const float*)d_in[3];
    const float* pemb = (const float*)d_in[4];
    const float* temb = (const float*)d_in[5];
    const float* Wfc  = (const float*)d_in[6];
    const float* bfc  = (const float*)d_in[7];
    const float* watt = (const float*)d_in[8];
    const float* batt = (const float*)d_in[9];
    float* out = (float*)d_out;

    cudaFuncSetAttribute(gemm_softmax_kernel<false>,
                         cudaFuncAttributeMaxDynamicSharedMemorySize, SMEM_K3_TOTAL);
    cudaFuncSetAttribute(gemm_softmax_kernel<true>,
                         cudaFuncAttributeMaxDynamicSharedMemorySize, SMEM_K3_TOTAL);

    // Launch order: ncu -s 5 -c 1 lands on the 4th launch -> gemmB.
    context_kernel<<<BATCH, 128>>>(v1i, pthi, v2i, vemb, pemb, temb,
                                   Wfc, bfc, watt, batt);

    dim3 grid(NGROUPS, BATCH / 128);
    gemm_softmax_kernel<false><<<grid, 256, SMEM_K3_TOTAL>>>(nullptr);
    reduce_kernel<<<BATCH / 8, 256>>>();
    gemm_softmax_kernel<true><<<grid, 256, SMEM_K3_TOTAL>>>(out);
}